// round 14
// baseline (speedup 1.0000x reference)
#include <cuda_runtime.h>

// ---------------------------------------------------------------------------
// Elman RNN (relu), B=64, T=512, I=64, H=1024, O=64
// out = [ hidden_list (B,T,H) | output_list (B,T,O) | h_last (1,B,H) ]
// ---------------------------------------------------------------------------

#define B_   64
#define T_   512
#define I_   64
#define H_   1024
#define O_   64

#define HID_OFF  0
#define OUT_OFF  (B_ * T_ * H_)              // 33554432
#define HL_OFF   (OUT_OFF + B_ * T_ * O_)    // 35651584

#define NBLK 128        // persistent blocks (1/SM)
#define TB   256        // 2 warps / SMSP

// SMEM layout (floats): 32 K-chunks of 32 floats padded to 34; row stride
// 1090 (not 1088) so 8*HRow = 34880 B = 64 mod 128 -> batch/col-octet offsets
// land on different banks under the warp-owns-K mapping.
#define CH    34
#define HRow  1090

// scratch: h double buffer + per-(group,block) flags (128B stride)
__device__ __align__(16) float g_hbuf[2][B_ * H_];
__device__ unsigned g_flag[4][32][32];

typedef unsigned long long ull;
typedef ulonglong2 ull2;

__device__ __forceinline__ ull f2fma(ull a, ull b, ull c) {
    ull d;
    asm("fma.rn.f32x2 %0, %1, %2, %3;" : "=l"(d) : "l"(a), "l"(b), "l"(c));
    return d;
}
__device__ __forceinline__ ull f2add(ull a, ull b) {
    ull d;
    asm("add.rn.f32x2 %0, %1, %2;" : "=l"(d) : "l"(a), "l"(b));
    return d;
}
__device__ __forceinline__ float pairsum(ull a) {
    float lo = __uint_as_float((unsigned)(a & 0xffffffffull));
    float hi = __uint_as_float((unsigned)(a >> 32));
    return lo + hi;
}
__device__ __forceinline__ unsigned ld_acq(unsigned* p) {
    unsigned v;
    asm volatile("ld.acquire.gpu.u32 %0, [%1];" : "=r"(v) : "l"(p) : "memory");
    return v;
}
__device__ __forceinline__ void st_rel(unsigned* p, unsigned v) {
    asm volatile("st.release.gpu.u32 [%0], %1;" :: "l"(p), "r"(v) : "memory");
}

// ---------------------------------------------------------------------------
// Kernel A: xw[bt][h] = x[bt]·W_ih[h] + b_ih[h] + b_hh[h]  -> hidden region
// f32x2 version. Block (0,0) zeroes flags.
// ---------------------------------------------------------------------------
__global__ void __launch_bounds__(256) xw_kernel(
    const float* __restrict__ x, const float* __restrict__ Wih,
    const float* __restrict__ bih, const float* __restrict__ bhh,
    float* __restrict__ hid_out)
{
    __shared__ float xs[64 * 66];
    __shared__ float ws[64 * 66];

    const int tid = threadIdx.x;
    const int hb  = blockIdx.x * 64;
    const int btb = blockIdx.y * 64;

    if (blockIdx.x == 0 && blockIdx.y == 0) {
        #pragma unroll
        for (int i = tid; i < 4 * 32 * 32; i += 256)
            ((unsigned*)g_flag)[i] = 0;
    }

    const float2* x2 = (const float2*)x;
    const float2* w2 = (const float2*)Wih;
    #pragma unroll
    for (int i = tid; i < 64 * 32; i += 256) {
        int r = i >> 5, q = i & 31;
        *(float2*)&xs[r * 66 + 2 * q] = x2[(btb + r) * 32 + q];
        *(float2*)&ws[r * 66 + 2 * q] = w2[(hb + r) * 32 + q];
    }
    __syncthreads();

    const int tx = tid & 15, ty = tid >> 4;
    ull acc[4][4];
    #pragma unroll
    for (int i = 0; i < 4; ++i)
        #pragma unroll
        for (int j = 0; j < 4; ++j) acc[i][j] = 0ull;

    #pragma unroll 8
    for (int k2 = 0; k2 < 32; ++k2) {
        ull a[4], b[4];
        #pragma unroll
        for (int i = 0; i < 4; ++i)
            a[i] = *(const ull*)&xs[(ty + 16 * i) * 66 + 2 * k2];
        #pragma unroll
        for (int j = 0; j < 4; ++j)
            b[j] = *(const ull*)&ws[(tx + 16 * j) * 66 + 2 * k2];
        #pragma unroll
        for (int i = 0; i < 4; ++i)
            #pragma unroll
            for (int j = 0; j < 4; ++j)
                acc[i][j] = f2fma(a[i], b[j], acc[i][j]);
    }

    #pragma unroll
    for (int j = 0; j < 4; ++j) {
        int h = hb + tx + 16 * j;
        float bb = bih[h] + bhh[h];
        #pragma unroll
        for (int i = 0; i < 4; ++i) {
            int bt = btb + ty + 16 * i;
            hid_out[bt * H_ + h] = pairsum(acc[i][j]) + bb;
        }
    }
}

// ---------------------------------------------------------------------------
// Kernel B: persistent recurrence, warp-owns-K dataflow.
// 128 blocks = 4 batch-groups(16) x 32 col-groups(32).
// Warp p owns K-range [128p,128p+128) = chunks 4p..4p+3 = EXACTLY the quad
// it polls (lanes 0-3) and stages -> no block barrier before FMA; warps run
// decoupled. Lane (ko=lane&3, t=lane>>2): chunk 4p+ko, tile t (pm=t&1 batch
// octet, pn=t>>1 col quarter), 8x8 f2fma over 32 K. 2-round ko-butterfly ->
// 16 outputs/lane -> partials into own dead hsm quad (conflict-free) ->
// one __syncthreads -> 8-warp f2add reduce -> relu epilogue -> bar split +
// flag release (R13 mechanism).
// ---------------------------------------------------------------------------
__global__ void __launch_bounds__(TB, 1) rnn_recur(
    const float* __restrict__ hid_in,
    const float* __restrict__ Whh,
    float* __restrict__ out)
{
    extern __shared__ float sm[];
    float* wsm = sm;                 // 32 rows x HRow
    float* hsm = sm + 32 * HRow;     // 16 rows x HRow (also partial buffer)

    const int tid = threadIdx.x;
    const int bi  = blockIdx.x >> 5;
    const int ci  = blockIdx.x & 31;
    const int b0  = bi * 16;
    const int c0  = ci * 32;

    const int lane = tid & 31;
    const int p    = tid >> 5;         // warp id: K-range / producer quad
    const int ko   = lane & 3;         // K-subchunk within quad
    const int t    = lane >> 2;        // output tile 0..7
    const int pm   = t & 1;            // batch octet
    const int pn   = t >> 1;           // col quarter (0..3)

    // ---- stage W_hh slice once: rows c0..c0+31, chunked layout ----
    const float2* W2 = (const float2*)Whh;
    #pragma unroll 4
    for (int i = tid; i < 32 * 512; i += TB) {
        int r = i >> 9, q = i & 511;
        *(float2*)&wsm[r * HRow + (q >> 4) * CH + (q & 15) * 2] =
            __ldg(&W2[(c0 + r) * 512 + q]);
    }

    const float* hb_ = hsm + pm * 8 * HRow + (4 * p + ko) * CH;
    const float* wb_ = wsm + pn * 8 * HRow + (4 * p + ko) * CH;

    float* hid_out = out + HID_OFF;
    float* hlast   = out + HL_OFF;

    // epilogue/reader mapping: this thread owns outputs (tile p_r = p,
    // o_local = 2*lane, 2*lane+1)
    const int te  = p;                 // reader tile = own warp id
    const int gb  = b0 + (te & 1) * 8 + (lane >> 2);
    const int gc  = c0 + (te >> 1) * 8 + 2 * (lane & 3);

    // partial-store base: c2 = 4t+ko, region = own quad chunks 4p..4p+1
    const int c2w = 4 * t + ko;
    float* prt_w = hsm + (c2w >> 1) * HRow + (4 * p) * CH + 16 * (c2w & 1);

    // reader base for outputs (te, 2*lane): ko_r = lane>>3, v = 2*(lane&7)
    const int c2r = 4 * te + (lane >> 3);
    const float* prt_r = hsm + (c2r >> 1) * HRow + 16 * (c2r & 1) + 2 * (lane & 7);

    // staging: warp p owns chunks 4p..4p+3; lane -> (cc = lane>>3, f4 = lane&7)
    const int st_cc = lane >> 3;
    const int st_f4 = lane & 7;

    #pragma unroll 1
    for (int s = 0; s < T_; ++s) {
        // prefetch xw for this thread's two outputs (own location)
        float2 xw = *(const float2*)&hid_out[((size_t)gb * T_ + s) * H_ + gc];

        // ---- per-warp parallel poll: producers 4p..4p+3 + own flag ----
        if (s > 0) {
            if (lane < 4) {
                unsigned* fp = &g_flag[bi][4 * p + lane][0];
                while ((int)(ld_acq(fp) - (unsigned)s) < 0) { }
            } else if (lane == 4) {
                unsigned* fp = &g_flag[bi][ci][0];
                while ((int)(ld_acq(fp) - (unsigned)s) < 0) { }
            }
            __syncwarp();
        }

        // ---- stage own quad: rows 0..15, chunks 4p..4p+3 ----
        const float4* hsrc = (s == 0) ? (const float4*)hid_in
                                      : (const float4*)g_hbuf[(s - 1) & 1];
        #pragma unroll
        for (int r = 0; r < 16; ++r) {
            float4 v = __ldcg(&hsrc[(b0 + r) * 256 + (4 * p + st_cc) * 8 + st_f4]);
            float* dst = &hsm[r * HRow + (4 * p + st_cc) * CH + st_f4 * 4];
            *(float2*)dst       = make_float2(v.x, v.y);
            *(float2*)(dst + 2) = make_float2(v.z, v.w);
        }
        __syncwarp();       // own warp staged own quad -> FMA may start

        // ---- 8x8 tile over private 32-K chunk (decoupled per warp) ----
        ull acc[64];
        #pragma unroll
        for (int i = 0; i < 64; ++i) acc[i] = 0ull;

        #pragma unroll
        for (int k2 = 0; k2 < 16; ++k2) {
            ull hv[8];
            #pragma unroll
            for (int i = 0; i < 8; ++i)
                hv[i] = *(const ull*)(hb_ + i * HRow + k2 * 2);
            ull wv[4];
            #pragma unroll
            for (int j = 0; j < 4; ++j)
                wv[j] = *(const ull*)(wb_ + j * HRow + k2 * 2);
            #pragma unroll
            for (int i = 0; i < 8; ++i)
                #pragma unroll
                for (int j = 0; j < 4; ++j)
                    acc[i * 8 + j] = f2fma(hv[i], wv[j], acc[i * 8 + j]);
            #pragma unroll
            for (int j = 0; j < 4; ++j)
                wv[j] = *(const ull*)(wb_ + (j + 4) * HRow + k2 * 2);
            #pragma unroll
            for (int i = 0; i < 8; ++i)
                #pragma unroll
                for (int j = 0; j < 4; ++j)
                    acc[i * 8 + j + 4] = f2fma(hv[i], wv[j], acc[i * 8 + j + 4]);
        }

        // ---- pairsum then 2-round butterfly over ko (masks 2, 1) ----
        float vals[64];
        #pragma unroll
        for (int v = 0; v < 64; ++v) vals[v] = pairsum(acc[v]);

        #pragma unroll
        for (int m = 2, cnt = 32; m >= 1; m >>= 1, cnt >>= 1) {
            bool up = (lane & m) != 0;
            #pragma unroll
            for (int i = 0; i < 32; ++i) {
                if (i >= cnt) break;
                float send = up ? vals[i] : vals[i + cnt];
                float keep = up ? vals[i + cnt] : vals[i];
                float recv = __shfl_xor_sync(0xffffffffu, send, m);
                vals[i] = keep + recv;
            }
        }
        // lane holds vals[0..15] = outputs o_local in [16*ko, 16*ko+16) of tile t

        // ---- write partials into own (dead) hsm quad region ----
        #pragma unroll
        for (int v = 0; v < 16; v += 2)
            *(float2*)(prt_w + v) = make_float2(vals[v], vals[v + 1]);
        __syncthreads();   // single block rendezvous per step

        // ---- final reduce: 8 warp-partials per output pair ----
        ull a2 = *(const ull*)(prt_r);
        #pragma unroll
        for (int q = 1; q < 8; ++q)
            a2 = f2add(a2, *(const ull*)(prt_r + q * 4 * CH));
        float v0 = pairsum(make_ulonglong2(a2, 0).x & 0xffffffffull
                           ? a2 & 0xffffffffull : 0ull);   // (unused guard)
        // unpack
        float lo = __uint_as_float((unsigned)(a2 & 0xffffffffull));
        float hi = __uint_as_float((unsigned)(a2 >> 32));

        float2 rr;
        rr.x = fmaxf(xw.x + lo, 0.0f);
        rr.y = fmaxf(xw.y + hi, 0.0f);

        *(float2*)&hid_out[((size_t)gb * T_ + s) * H_ + gc] = rr;
        *(float2*)&g_hbuf[s & 1][gb * H_ + gc] = rr;
        if (s == T_ - 1)
            *(float2*)&hlast[gb * H_ + gc] = rr;

        // ---- epilogue rendezvous: warps 1..7 arrive, warp 0 syncs+releases
        if (s != T_ - 1) {
            if (p == 0) {
                asm volatile("bar.sync 1, %0;" :: "n"(TB) : "memory");
                if (tid == 0)
                    st_rel(&g_flag[bi][ci][0], (unsigned)(s + 1));
            } else {
                asm volatile("bar.arrive 1, %0;" :: "n"(TB) : "memory");
            }
        }
    }
}

// ---------------------------------------------------------------------------
// Kernel C: output_list[bt][o] = hid[bt]·W_out[o] + b_out[o]   (f32x2)
// 64x64 tile, 256 threads, cp.async double-buffered, FULL K (32 chunks).
// ---------------------------------------------------------------------------
#define OC 36           // chunk row stride (32 + 4 pad, 16B-aligned)

__device__ __forceinline__ void cp16(unsigned dst, const void* src) {
    asm volatile("cp.async.cg.shared.global [%0], [%1], 16;"
                 :: "r"(dst), "l"(src) : "memory");
}
__device__ __forceinline__ void cp_commit() {
    asm volatile("cp.async.commit_group;" ::: "memory");
}

__global__ void __launch_bounds__(256) out_kernel(
    const float* __restrict__ hid, const float* __restrict__ Wout,
    const float* __restrict__ bout, float* __restrict__ outp)
{
    __shared__ float hs[2][64 * OC];
    __shared__ float ws2[2][64 * OC];

    const int tid = threadIdx.x;
    const int btb = blockIdx.x * 64;
    const int tx = tid & 15, ty = tid >> 4;

    const float4* hid4  = (const float4*)hid;
    const float4* wout4 = (const float4*)Wout;

    const unsigned hs_base  = (unsigned)__cvta_generic_to_shared(&hs[0][0]);
    const unsigned ws_base  = (unsigned)__cvta_generic_to_shared(&ws2[0][0]);
    const unsigned buf_step = 64 * OC * 4;

    auto issue = [&](int c, int b) {
        #pragma unroll
        for (int k = 0; k < 2; ++k) {
            int idx = k * 256 + tid;
            int r = idx >> 3, f = idx & 7;
            unsigned off = (unsigned)(r * OC + f * 4) * 4u + (unsigned)b * buf_step;
            cp16(hs_base + off, &hid4[(btb + r) * 256 + c * 8 + f]);
            cp16(ws_base + off, &wout4[r * 256 + c * 8 + f]);
        }
        cp_commit();
    };

    ull acc[4][4];
    #pragma unroll
    for (int i = 0; i < 4; ++i)
        #pragma unroll
        for (int j = 0; j < 4; ++j) acc[i][j] = 0ull;

    issue(0, 0);
    issue(1, 1);

    #pragma unroll 1
    for (int c = 0; c < 32; ++c) {
        if (c < 31) asm volatile("cp.async.wait_group 1;" ::: "memory");
        else        asm volatile("cp.async.wait_group 0;" ::: "memory");
        __syncthreads();

        const int b = c & 1;
        const float* hb = &hs[b][0];
        const float* wb = &ws2[b][0];

        #pragma unroll
        for (int k4 = 0; k4 < 8; ++k4) {
            ull2 a2[4], b2[4];
            #pragma unroll
            for (int i = 0; i < 4; ++i)
                a2[i] = *(const ull2*)&hb[(ty + 16 * i) * OC + k4 * 4];
            #pragma unroll
            for (int j = 0; j < 4; ++j)
                b2[j] = *(const ull2*)&wb[(tx + 16 * j) * OC + k4 * 4];
            #pragma unroll
            for (int i = 0; i < 4; ++i)
                #pragma unroll
                for (int j = 0; j < 4; ++j) {
                    acc[i][j] = f2fma(a2[i].x, b2[j].x, acc[i][j]);
                    acc[i][j] = f2fma(a2[i].y, b2[j].y, acc[i][j]);
                }
        }
        __syncthreads();

        if (c < 30) issue(c + 2, b);
    }

    #pragma unroll
    for (int j = 0; j < 4; ++j) {
        int o = tx + 16 * j;
        float bb = bout[o];
        #pragma unroll
        for (int i = 0; i < 4; ++i)
            outp[(btb + ty + 16 * i) * O_ + o] = pairsum(acc[i][j]) + bb;
    }
}

// ---------------------------------------------------------------------------
extern "C" void kernel_launch(void* const* d_in, const int* in_sizes, int n_in,
                              void* d_out, int out_size) {
    const float* x      = (const float*)d_in[0];
    const float* hidden = (const float*)d_in[1];
    const float* W_ih   = (const float*)d_in[2];
    const float* W_hh   = (const float*)d_in[3];
    const float* b_ih   = (const float*)d_in[4];
    const float* b_hh   = (const float*)d_in[5];
    const float* W_out  = (const float*)d_in[6];
    const float* b_out  = (const float*)d_in[7];
    float* out = (float*)d_out;

    dim3 gA(H_ / 64, (B_ * T_) / 64);
    xw_kernel<<<gA, 256>>>(x, W_ih, b_ih, b_hh, out + HID_OFF);

    size_t smemB = (size_t)(48 * HRow) * sizeof(float);   // 209,280 B
    cudaFuncSetAttribute(rnn_recur, cudaFuncAttributeMaxDynamicSharedMemorySize,
                         (int)smemB);
    rnn_recur<<<NBLK, TB, smemB>>>(hidden, W_hh, out);

    out_kernel<<<(B_ * T_) / 64, 256>>>(out + HID_OFF, W_out, b_out, out + OUT_OFF);
}

// round 15
// speedup vs baseline: 1.0709x; 1.0709x over previous
#include <cuda_runtime.h>

// ---------------------------------------------------------------------------
// Elman RNN (relu), B=64, T=512, I=64, H=1024, O=64
// out = [ hidden_list (B,T,H) | output_list (B,T,O) | h_last (1,B,H) ]
// ---------------------------------------------------------------------------

#define B_   64
#define T_   512
#define I_   64
#define H_   1024
#define O_   64

#define HID_OFF  0
#define OUT_OFF  (B_ * T_ * H_)              // 33554432
#define HL_OFF   (OUT_OFF + B_ * T_ * O_)    // 35651584

#define NBLK 128        // persistent blocks (1/SM)
#define TB   256        // 2 warps / SMSP

// SMEM layout (floats): 32 K-chunks of 32 floats padded to 34; row stride
// 1090; W col-octets skewed by WQ = 8*HRow + 8 so the four octet bases map
// to byte offsets {0,96,64,32} mod 128 -> conflict-free wv loads.
#define CH    34
#define HRow  1090
#define WQ    (8 * HRow + 8)    // 8728 floats per W col-octet region

// scratch: h double buffer + per-(group,block) flags (128B stride)
__device__ __align__(16) float g_hbuf[2][B_ * H_];
__device__ unsigned g_flag[4][32][32];

typedef unsigned long long ull;
typedef ulonglong2 ull2;

__device__ __forceinline__ ull f2fma(ull a, ull b, ull c) {
    ull d;
    asm("fma.rn.f32x2 %0, %1, %2, %3;" : "=l"(d) : "l"(a), "l"(b), "l"(c));
    return d;
}
__device__ __forceinline__ ull f2add(ull a, ull b) {
    ull d;
    asm("add.rn.f32x2 %0, %1, %2;" : "=l"(d) : "l"(a), "l"(b));
    return d;
}
__device__ __forceinline__ float pairsum(ull a) {
    float lo = __uint_as_float((unsigned)(a & 0xffffffffull));
    float hi = __uint_as_float((unsigned)(a >> 32));
    return lo + hi;
}
__device__ __forceinline__ unsigned ld_acq(unsigned* p) {
    unsigned v;
    asm volatile("ld.acquire.gpu.u32 %0, [%1];" : "=r"(v) : "l"(p) : "memory");
    return v;
}
__device__ __forceinline__ void st_rel(unsigned* p, unsigned v) {
    asm volatile("st.release.gpu.u32 [%0], %1;" :: "l"(p), "r"(v) : "memory");
}

// ---------------------------------------------------------------------------
// Kernel A: xw[bt][h] = x[bt]·W_ih[h] + b_ih[h] + b_hh[h]  -> hidden region
// f32x2 version. Block (0,0) zeroes flags.
// ---------------------------------------------------------------------------
__global__ void __launch_bounds__(256) xw_kernel(
    const float* __restrict__ x, const float* __restrict__ Wih,
    const float* __restrict__ bih, const float* __restrict__ bhh,
    float* __restrict__ hid_out)
{
    __shared__ float xs[64 * 66];
    __shared__ float ws[64 * 66];

    const int tid = threadIdx.x;
    const int hb  = blockIdx.x * 64;
    const int btb = blockIdx.y * 64;

    if (blockIdx.x == 0 && blockIdx.y == 0) {
        #pragma unroll
        for (int i = tid; i < 4 * 32 * 32; i += 256)
            ((unsigned*)g_flag)[i] = 0;
    }

    const float2* x2 = (const float2*)x;
    const float2* w2 = (const float2*)Wih;
    #pragma unroll
    for (int i = tid; i < 64 * 32; i += 256) {
        int r = i >> 5, q = i & 31;
        *(float2*)&xs[r * 66 + 2 * q] = x2[(btb + r) * 32 + q];
        *(float2*)&ws[r * 66 + 2 * q] = w2[(hb + r) * 32 + q];
    }
    __syncthreads();

    const int tx = tid & 15, ty = tid >> 4;
    ull acc[4][4];
    #pragma unroll
    for (int i = 0; i < 4; ++i)
        #pragma unroll
        for (int j = 0; j < 4; ++j) acc[i][j] = 0ull;

    #pragma unroll 8
    for (int k2 = 0; k2 < 32; ++k2) {
        ull a[4], b[4];
        #pragma unroll
        for (int i = 0; i < 4; ++i)
            a[i] = *(const ull*)&xs[(ty + 16 * i) * 66 + 2 * k2];
        #pragma unroll
        for (int j = 0; j < 4; ++j)
            b[j] = *(const ull*)&ws[(tx + 16 * j) * 66 + 2 * k2];
        #pragma unroll
        for (int i = 0; i < 4; ++i)
            #pragma unroll
            for (int j = 0; j < 4; ++j)
                acc[i][j] = f2fma(a[i], b[j], acc[i][j]);
    }

    #pragma unroll
    for (int j = 0; j < 4; ++j) {
        int h = hb + tx + 16 * j;
        float bb = bih[h] + bhh[h];
        #pragma unroll
        for (int i = 0; i < 4; ++i) {
            int bt = btb + ty + 16 * i;
            hid_out[bt * H_ + h] = pairsum(acc[i][j]) + bb;
        }
    }
}

// ---------------------------------------------------------------------------
// Kernel B: persistent recurrence, warp-owns-K dataflow (R14 + W skew fix).
// 128 blocks = 4 batch-groups(16) x 32 col-groups(32).
// Warp p owns K-chunks 4p..4p+3 = exactly the producer quad it polls and
// stages -> per-warp decoupled poll/stage/FMA. Lane (ko=lane&3, t=lane>>2):
// chunk 4p+ko, tile t (pm=t&1 batch octet, pn=t>>1 col quarter). W stored
// with per-octet skew WQ -> wv loads conflict-free. 2-round ko-butterfly ->
// partials in dead hsm quad -> one __syncthreads -> 8-warp f2add reduce ->
// relu epilogue -> bar split + flag release.
// ---------------------------------------------------------------------------
__global__ void __launch_bounds__(TB, 1) rnn_recur(
    const float* __restrict__ hid_in,
    const float* __restrict__ Whh,
    float* __restrict__ out)
{
    extern __shared__ float sm[];
    float* wsm = sm;                 // 4 octet regions x WQ floats
    float* hsm = sm + 4 * WQ;        // 16 rows x HRow (also partial buffer)

    const int tid = threadIdx.x;
    const int bi  = blockIdx.x >> 5;
    const int ci  = blockIdx.x & 31;
    const int b0  = bi * 16;
    const int c0  = ci * 32;

    const int lane = tid & 31;
    const int p    = tid >> 5;         // warp id: K-range / producer quad
    const int ko   = lane & 3;         // K-subchunk within quad
    const int t    = lane >> 2;        // output tile 0..7
    const int pm   = t & 1;            // batch octet
    const int pn   = t >> 1;           // col quarter (0..3)

    // ---- stage W_hh slice once: rows c0..c0+31, skewed octet layout ----
    const float2* W2 = (const float2*)Whh;
    #pragma unroll 4
    for (int i = tid; i < 32 * 512; i += TB) {
        int r = i >> 9, q = i & 511;
        *(float2*)&wsm[(r >> 3) * WQ + (r & 7) * HRow + (q >> 4) * CH + (q & 15) * 2] =
            __ldg(&W2[(c0 + r) * 512 + q]);
    }

    const float* hb_ = hsm + pm * 8 * HRow + (4 * p + ko) * CH;
    const float* wb_ = wsm + pn * WQ + (4 * p + ko) * CH;

    float* hid_out = out + HID_OFF;
    float* hlast   = out + HL_OFF;

    // epilogue/reader mapping: thread owns outputs (tile te = p, 2*lane..+1)
    const int te  = p;
    const int gb  = b0 + (te & 1) * 8 + (lane >> 2);
    const int gc  = c0 + (te >> 1) * 8 + 2 * (lane & 3);

    // partial-store base: c2 = 4t+ko, region = own quad chunks (4p..)
    const int c2w = 4 * t + ko;
    float* prt_w = hsm + (c2w >> 1) * HRow + (4 * p) * CH + 16 * (c2w & 1);

    // reader base for outputs (te, 2*lane)
    const int c2r = 4 * te + (lane >> 3);
    const float* prt_r = hsm + (c2r >> 1) * HRow + 16 * (c2r & 1) + 2 * (lane & 7);

    // staging: warp p owns chunks 4p..4p+3; lane -> (cc = lane>>3, f4 = lane&7)
    const int st_cc = lane >> 3;
    const int st_f4 = lane & 7;

    #pragma unroll 1
    for (int s = 0; s < T_; ++s) {
        // prefetch xw for this thread's two outputs (own location)
        float2 xw = *(const float2*)&hid_out[((size_t)gb * T_ + s) * H_ + gc];

        // ---- per-warp parallel poll: producers 4p..4p+3 + own flag ----
        if (s > 0) {
            if (lane < 4) {
                unsigned* fp = &g_flag[bi][4 * p + lane][0];
                while ((int)(ld_acq(fp) - (unsigned)s) < 0) { }
            } else if (lane == 4) {
                unsigned* fp = &g_flag[bi][ci][0];
                while ((int)(ld_acq(fp) - (unsigned)s) < 0) { }
            }
            __syncwarp();
        }

        // ---- stage own quad: rows 0..15, chunks 4p..4p+3 ----
        const float4* hsrc = (s == 0) ? (const float4*)hid_in
                                      : (const float4*)g_hbuf[(s - 1) & 1];
        #pragma unroll
        for (int r = 0; r < 16; ++r) {
            float4 v = __ldcg(&hsrc[(b0 + r) * 256 + (4 * p + st_cc) * 8 + st_f4]);
            float* dst = &hsm[r * HRow + (4 * p + st_cc) * CH + st_f4 * 4];
            *(float2*)dst       = make_float2(v.x, v.y);
            *(float2*)(dst + 2) = make_float2(v.z, v.w);
        }
        __syncwarp();       // own warp staged own quad -> FMA may start

        // ---- 8x8 tile over private 32-K chunk (decoupled per warp) ----
        ull acc[64];
        #pragma unroll
        for (int i = 0; i < 64; ++i) acc[i] = 0ull;

        #pragma unroll
        for (int k2 = 0; k2 < 16; ++k2) {
            ull hv[8];
            #pragma unroll
            for (int i = 0; i < 8; ++i)
                hv[i] = *(const ull*)(hb_ + i * HRow + k2 * 2);
            ull wv[4];
            #pragma unroll
            for (int j = 0; j < 4; ++j)
                wv[j] = *(const ull*)(wb_ + j * HRow + k2 * 2);
            #pragma unroll
            for (int i = 0; i < 8; ++i)
                #pragma unroll
                for (int j = 0; j < 4; ++j)
                    acc[i * 8 + j] = f2fma(hv[i], wv[j], acc[i * 8 + j]);
            #pragma unroll
            for (int j = 0; j < 4; ++j)
                wv[j] = *(const ull*)(wb_ + (j + 4) * HRow + k2 * 2);
            #pragma unroll
            for (int i = 0; i < 8; ++i)
                #pragma unroll
                for (int j = 0; j < 4; ++j)
                    acc[i * 8 + j + 4] = f2fma(hv[i], wv[j], acc[i * 8 + j + 4]);
        }

        // ---- pairsum then 2-round butterfly over ko (masks 2, 1) ----
        float vals[64];
        #pragma unroll
        for (int v = 0; v < 64; ++v) vals[v] = pairsum(acc[v]);

        #pragma unroll
        for (int m = 2, cnt = 32; m >= 1; m >>= 1, cnt >>= 1) {
            bool up = (lane & m) != 0;
            #pragma unroll
            for (int i = 0; i < 32; ++i) {
                if (i >= cnt) break;
                float send = up ? vals[i] : vals[i + cnt];
                float keep = up ? vals[i + cnt] : vals[i];
                float recv = __shfl_xor_sync(0xffffffffu, send, m);
                vals[i] = keep + recv;
            }
        }
        // lane holds vals[0..15] = outputs [16*ko,16*ko+16) of tile t

        // ---- write partials into own (dead) hsm quad region ----
        #pragma unroll
        for (int v = 0; v < 16; v += 2)
            *(float2*)(prt_w + v) = make_float2(vals[v], vals[v + 1]);
        __syncthreads();   // single block rendezvous per step

        // ---- final reduce: 8 warp-partials per output pair ----
        ull a2 = *(const ull*)(prt_r);
        #pragma unroll
        for (int q = 1; q < 8; ++q)
            a2 = f2add(a2, *(const ull*)(prt_r + q * 4 * CH));
        float lo = __uint_as_float((unsigned)(a2 & 0xffffffffull));
        float hi = __uint_as_float((unsigned)(a2 >> 32));

        float2 rr;
        rr.x = fmaxf(xw.x + lo, 0.0f);
        rr.y = fmaxf(xw.y + hi, 0.0f);

        *(float2*)&hid_out[((size_t)gb * T_ + s) * H_ + gc] = rr;
        *(float2*)&g_hbuf[s & 1][gb * H_ + gc] = rr;
        if (s == T_ - 1)
            *(float2*)&hlast[gb * H_ + gc] = rr;

        // ---- epilogue rendezvous: warps 1..7 arrive, warp 0 syncs+releases
        if (s != T_ - 1) {
            if (p == 0) {
                asm volatile("bar.sync 1, %0;" :: "n"(TB) : "memory");
                if (tid == 0)
                    st_rel(&g_flag[bi][ci][0], (unsigned)(s + 1));
            } else {
                asm volatile("bar.arrive 1, %0;" :: "n"(TB) : "memory");
            }
        }
    }
}

// ---------------------------------------------------------------------------
// Kernel C: output_list[bt][o] = hid[bt]·W_out[o] + b_out[o]   (f32x2)
// 64x64 tile, 256 threads, cp.async double-buffered, FULL K (32 chunks).
// ---------------------------------------------------------------------------
#define OC 36           // chunk row stride (32 + 4 pad, 16B-aligned)

__device__ __forceinline__ void cp16(unsigned dst, const void* src) {
    asm volatile("cp.async.cg.shared.global [%0], [%1], 16;"
                 :: "r"(dst), "l"(src) : "memory");
}
__device__ __forceinline__ void cp_commit() {
    asm volatile("cp.async.commit_group;" ::: "memory");
}

__global__ void __launch_bounds__(256) out_kernel(
    const float* __restrict__ hid, const float* __restrict__ Wout,
    const float* __restrict__ bout, float* __restrict__ outp)
{
    __shared__ float hs[2][64 * OC];
    __shared__ float ws2[2][64 * OC];

    const int tid = threadIdx.x;
    const int btb = blockIdx.x * 64;
    const int tx = tid & 15, ty = tid >> 4;

    const float4* hid4  = (const float4*)hid;
    const float4* wout4 = (const float4*)Wout;

    const unsigned hs_base  = (unsigned)__cvta_generic_to_shared(&hs[0][0]);
    const unsigned ws_base  = (unsigned)__cvta_generic_to_shared(&ws2[0][0]);
    const unsigned buf_step = 64 * OC * 4;

    auto issue = [&](int c, int b) {
        #pragma unroll
        for (int k = 0; k < 2; ++k) {
            int idx = k * 256 + tid;
            int r = idx >> 3, f = idx & 7;
            unsigned off = (unsigned)(r * OC + f * 4) * 4u + (unsigned)b * buf_step;
            cp16(hs_base + off, &hid4[(btb + r) * 256 + c * 8 + f]);
            cp16(ws_base + off, &wout4[r * 256 + c * 8 + f]);
        }
        cp_commit();
    };

    ull acc[4][4];
    #pragma unroll
    for (int i = 0; i < 4; ++i)
        #pragma unroll
        for (int j = 0; j < 4; ++j) acc[i][j] = 0ull;

    issue(0, 0);
    issue(1, 1);

    #pragma unroll 1
    for (int c = 0; c < 32; ++c) {
        if (c < 31) asm volatile("cp.async.wait_group 1;" ::: "memory");
        else        asm volatile("cp.async.wait_group 0;" ::: "memory");
        __syncthreads();

        const int b = c & 1;
        const float* hb = &hs[b][0];
        const float* wb = &ws2[b][0];

        #pragma unroll
        for (int k4 = 0; k4 < 8; ++k4) {
            ull2 a2[4], b2[4];
            #pragma unroll
            for (int i = 0; i < 4; ++i)
                a2[i] = *(const ull2*)&hb[(ty + 16 * i) * OC + k4 * 4];
            #pragma unroll
            for (int j = 0; j < 4; ++j)
                b2[j] = *(const ull2*)&wb[(tx + 16 * j) * OC + k4 * 4];
            #pragma unroll
            for (int i = 0; i < 4; ++i)
                #pragma unroll
                for (int j = 0; j < 4; ++j) {
                    acc[i][j] = f2fma(a2[i].x, b2[j].x, acc[i][j]);
                    acc[i][j] = f2fma(a2[i].y, b2[j].y, acc[i][j]);
                }
        }
        __syncthreads();

        if (c < 30) issue(c + 2, b);
    }

    #pragma unroll
    for (int j = 0; j < 4; ++j) {
        int o = tx + 16 * j;
        float bb = bout[o];
        #pragma unroll
        for (int i = 0; i < 4; ++i)
            outp[(btb + ty + 16 * i) * O_ + o] = pairsum(acc[i][j]) + bb;
    }
}

// ---------------------------------------------------------------------------
extern "C" void kernel_launch(void* const* d_in, const int* in_sizes, int n_in,
                              void* d_out, int out_size) {
    const float* x      = (const float*)d_in[0];
    const float* hidden = (const float*)d_in[1];
    const float* W_ih   = (const float*)d_in[2];
    const float* W_hh   = (const float*)d_in[3];
    const float* b_ih   = (const float*)d_in[4];
    const float* b_hh   = (const float*)d_in[5];
    const float* W_out  = (const float*)d_in[6];
    const float* b_out  = (const float*)d_in[7];
    float* out = (float*)d_out;

    dim3 gA(H_ / 64, (B_ * T_) / 64);
    xw_kernel<<<gA, 256>>>(x, W_ih, b_ih, b_hh, out + HID_OFF);

    // SMEM: 4*WQ + 16*HRow = 34912 + 17440 = 52352 floats = 209,408 B
    size_t smemB = (size_t)(4 * WQ + 16 * HRow) * sizeof(float);
    cudaFuncSetAttribute(rnn_recur, cudaFuncAttributeMaxDynamicSharedMemorySize,
                         (int)smemB);
    rnn_recur<<<NBLK, TB, smemB>>>(hidden, W_hh, out);

    out_kernel<<<(B_ * T_) / 64, 256>>>(out + HID_OFF, W_out, b_out, out + OUT_OFF);
}

// round 16
// speedup vs baseline: 1.0805x; 1.0090x over previous
#include <cuda_runtime.h>

// ---------------------------------------------------------------------------
// Elman RNN (relu), B=64, T=512, I=64, H=1024, O=64
// out = [ hidden_list (B,T,H) | output_list (B,T,O) | h_last (1,B,H) ]
// ---------------------------------------------------------------------------

#define B_   64
#define T_   512
#define I_   64
#define H_   1024
#define O_   64

#define HID_OFF  0
#define OUT_OFF  (B_ * T_ * H_)              // 33554432
#define HL_OFF   (OUT_OFF + B_ * T_ * O_)    // 35651584

#define NBLK 128        // persistent blocks (1/SM)
#define TB   256        // 2 warps / SMSP

// SMEM layout (floats): 32 K-chunks of 32 floats padded to 34; row stride
// 1090; W col-octets skewed by WQ so octet bases hit {0,96,64,32} mod 128.
#define CH    34
#define HRow  1090
#define WQ    (8 * HRow + 8)    // 8728 floats per W col-octet region

// per-(group,block) flags (128B stride)
__device__ unsigned g_flag[4][32][32];

typedef unsigned long long ull;
typedef ulonglong2 ull2;

__device__ __forceinline__ ull f2fma(ull a, ull b, ull c) {
    ull d;
    asm("fma.rn.f32x2 %0, %1, %2, %3;" : "=l"(d) : "l"(a), "l"(b), "l"(c));
    return d;
}
__device__ __forceinline__ ull f2add(ull a, ull b) {
    ull d;
    asm("add.rn.f32x2 %0, %1, %2;" : "=l"(d) : "l"(a), "l"(b));
    return d;
}
__device__ __forceinline__ float pairsum(ull a) {
    float lo = __uint_as_float((unsigned)(a & 0xffffffffull));
    float hi = __uint_as_float((unsigned)(a >> 32));
    return lo + hi;
}
__device__ __forceinline__ unsigned ld_acq(unsigned* p) {
    unsigned v;
    asm volatile("ld.acquire.gpu.u32 %0, [%1];" : "=r"(v) : "l"(p) : "memory");
    return v;
}
__device__ __forceinline__ void st_rel(unsigned* p, unsigned v) {
    asm volatile("st.release.gpu.u32 [%0], %1;" :: "l"(p), "r"(v) : "memory");
}

// ---------------------------------------------------------------------------
// Kernel A: xw[bt][h] = x[bt]·W_ih[h] + b_ih[h] + b_hh[h]  -> hidden region
// 128x64 block tile, 256 threads, 8x4 f32x2 micro-tile. Dynamic smem.
// Block (0,0) zeroes flags.
// ---------------------------------------------------------------------------
__global__ void __launch_bounds__(256) xw_kernel(
    const float* __restrict__ x, const float* __restrict__ Wih,
    const float* __restrict__ bih, const float* __restrict__ bhh,
    float* __restrict__ hid_out)
{
    extern __shared__ float axw[];
    float* xs = axw;                 // 128 rows x 66
    float* ws = axw + 128 * 66;      // 64 rows x 66

    const int tid = threadIdx.x;
    const int hb  = blockIdx.x * 64;
    const int btb = blockIdx.y * 128;

    if (blockIdx.x == 0 && blockIdx.y == 0) {
        #pragma unroll
        for (int i = tid; i < 4 * 32 * 32; i += 256)
            ((unsigned*)g_flag)[i] = 0;
    }

    const float2* x2 = (const float2*)x;
    const float2* w2 = (const float2*)Wih;
    #pragma unroll
    for (int k = 0; k < 16; ++k) {          // xs: 128 rows x 32 float2
        int idx = k * 256 + tid;
        int r = idx >> 5, q = idx & 31;
        *(float2*)&xs[r * 66 + 2 * q] = x2[(btb + r) * 32 + q];
    }
    #pragma unroll
    for (int k = 0; k < 8; ++k) {           // ws: 64 rows x 32 float2
        int idx = k * 256 + tid;
        int r = idx >> 5, q = idx & 31;
        *(float2*)&ws[r * 66 + 2 * q] = w2[(hb + r) * 32 + q];
    }
    __syncthreads();

    const int tx = tid & 15, ty = tid >> 4;
    ull acc[8][4];
    #pragma unroll
    for (int i = 0; i < 8; ++i)
        #pragma unroll
        for (int j = 0; j < 4; ++j) acc[i][j] = 0ull;

    #pragma unroll 4
    for (int k2 = 0; k2 < 32; ++k2) {
        ull a[8], b[4];
        #pragma unroll
        for (int i = 0; i < 8; ++i)
            a[i] = *(const ull*)&xs[(ty + 16 * i) * 66 + 2 * k2];
        #pragma unroll
        for (int j = 0; j < 4; ++j)
            b[j] = *(const ull*)&ws[(tx + 16 * j) * 66 + 2 * k2];
        #pragma unroll
        for (int i = 0; i < 8; ++i)
            #pragma unroll
            for (int j = 0; j < 4; ++j)
                acc[i][j] = f2fma(a[i], b[j], acc[i][j]);
    }

    #pragma unroll
    for (int j = 0; j < 4; ++j) {
        int h = hb + tx + 16 * j;
        float bb = bih[h] + bhh[h];
        #pragma unroll
        for (int i = 0; i < 8; ++i) {
            int bt = btb + ty + 16 * i;
            hid_out[bt * H_ + h] = pairsum(acc[i][j]) + bb;
        }
    }
}

// ---------------------------------------------------------------------------
// Kernel B: persistent recurrence, warp-owns-K dataflow (R15, no g_hbuf:
// h is staged directly from hid_out's step s-1 column).
// 128 blocks = 4 batch-groups(16) x 32 col-groups(32).
// ---------------------------------------------------------------------------
__global__ void __launch_bounds__(TB, 1) rnn_recur(
    const float* __restrict__ hid_in,
    const float* __restrict__ Whh,
    float* __restrict__ out)
{
    extern __shared__ float sm[];
    float* wsm = sm;                 // 4 octet regions x WQ floats
    float* hsm = sm + 4 * WQ;        // 16 rows x HRow (also partial buffer)

    const int tid = threadIdx.x;
    const int bi  = blockIdx.x >> 5;
    const int ci  = blockIdx.x & 31;
    const int b0  = bi * 16;
    const int c0  = ci * 32;

    const int lane = tid & 31;
    const int p    = tid >> 5;
    const int ko   = lane & 3;
    const int t    = lane >> 2;
    const int pm   = t & 1;
    const int pn   = t >> 1;

    // ---- stage W_hh slice once: rows c0..c0+31, skewed octet layout ----
    const float2* W2 = (const float2*)Whh;
    #pragma unroll 4
    for (int i = tid; i < 32 * 512; i += TB) {
        int r = i >> 9, q = i & 511;
        *(float2*)&wsm[(r >> 3) * WQ + (r & 7) * HRow + (q >> 4) * CH + (q & 15) * 2] =
            __ldg(&W2[(c0 + r) * 512 + q]);
    }

    const float* hb_ = hsm + pm * 8 * HRow + (4 * p + ko) * CH;
    const float* wb_ = wsm + pn * WQ + (4 * p + ko) * CH;

    float* hid_out = out + HID_OFF;
    float* hlast   = out + HL_OFF;

    const int te  = p;
    const int gb  = b0 + (te & 1) * 8 + (lane >> 2);
    const int gc  = c0 + (te >> 1) * 8 + 2 * (lane & 3);

    const int c2w = 4 * t + ko;
    float* prt_w = hsm + (c2w >> 1) * HRow + (4 * p) * CH + 16 * (c2w & 1);

    const int c2r = 4 * te + (lane >> 3);
    const float* prt_r = hsm + (c2r >> 1) * HRow + 16 * (c2r & 1) + 2 * (lane & 7);

    const int st_cc = lane >> 3;
    const int st_f4 = lane & 7;

    #pragma unroll 1
    for (int s = 0; s < T_; ++s) {
        // prefetch xw for this thread's two outputs (own location)
        float2 xw = *(const float2*)&hid_out[((size_t)gb * T_ + s) * H_ + gc];

        // ---- per-warp parallel poll: producers 4p..4p+3 + own flag ----
        if (s > 0) {
            if (lane < 4) {
                unsigned* fp = &g_flag[bi][4 * p + lane][0];
                while ((int)(ld_acq(fp) - (unsigned)s) < 0) { }
            } else if (lane == 4) {
                unsigned* fp = &g_flag[bi][ci][0];
                while ((int)(ld_acq(fp) - (unsigned)s) < 0) { }
            }
            __syncwarp();
        }

        // ---- stage own quad: rows 0..15, chunks 4p..4p+3 ----
        // s>0: read step s-1 hidden directly from hid_out (no g_hbuf)
        const float4* hsrc;
        size_t rstride;
        if (s == 0) {
            hsrc = (const float4*)hid_in + (size_t)b0 * 256;
            rstride = 256;
        } else {
            hsrc = (const float4*)hid_out + ((size_t)b0 * 512 + (s - 1)) * 256;
            rstride = (size_t)512 * 256;
        }
        #pragma unroll
        for (int r = 0; r < 16; ++r) {
            float4 v = __ldcg(&hsrc[r * rstride + (4 * p + st_cc) * 8 + st_f4]);
            float* dst = &hsm[r * HRow + (4 * p + st_cc) * CH + st_f4 * 4];
            *(float2*)dst       = make_float2(v.x, v.y);
            *(float2*)(dst + 2) = make_float2(v.z, v.w);
        }
        __syncwarp();

        // ---- 8x8 tile over private 32-K chunk (decoupled per warp) ----
        ull acc[64];
        #pragma unroll
        for (int i = 0; i < 64; ++i) acc[i] = 0ull;

        #pragma unroll
        for (int k2 = 0; k2 < 16; ++k2) {
            ull hv[8];
            #pragma unroll
            for (int i = 0; i < 8; ++i)
                hv[i] = *(const ull*)(hb_ + i * HRow + k2 * 2);
            ull wv[4];
            #pragma unroll
            for (int j = 0; j < 4; ++j)
                wv[j] = *(const ull*)(wb_ + j * HRow + k2 * 2);
            #pragma unroll
            for (int i = 0; i < 8; ++i)
                #pragma unroll
                for (int j = 0; j < 4; ++j)
                    acc[i * 8 + j] = f2fma(hv[i], wv[j], acc[i * 8 + j]);
            #pragma unroll
            for (int j = 0; j < 4; ++j)
                wv[j] = *(const ull*)(wb_ + (j + 4) * HRow + k2 * 2);
            #pragma unroll
            for (int i = 0; i < 8; ++i)
                #pragma unroll
                for (int j = 0; j < 4; ++j)
                    acc[i * 8 + j + 4] = f2fma(hv[i], wv[j], acc[i * 8 + j + 4]);
        }

        // ---- pairsum then 2-round butterfly over ko (masks 2, 1) ----
        float vals[64];
        #pragma unroll
        for (int v = 0; v < 64; ++v) vals[v] = pairsum(acc[v]);

        #pragma unroll
        for (int m = 2, cnt = 32; m >= 1; m >>= 1, cnt >>= 1) {
            bool up = (lane & m) != 0;
            #pragma unroll
            for (int i = 0; i < 32; ++i) {
                if (i >= cnt) break;
                float send = up ? vals[i] : vals[i + cnt];
                float keep = up ? vals[i + cnt] : vals[i];
                float recv = __shfl_xor_sync(0xffffffffu, send, m);
                vals[i] = keep + recv;
            }
        }

        // ---- write partials into own (dead) hsm quad region ----
        #pragma unroll
        for (int v = 0; v < 16; v += 2)
            *(float2*)(prt_w + v) = make_float2(vals[v], vals[v + 1]);
        __syncthreads();

        // ---- final reduce: 8 warp-partials per output pair ----
        ull a2 = *(const ull*)(prt_r);
        #pragma unroll
        for (int q = 1; q < 8; ++q)
            a2 = f2add(a2, *(const ull*)(prt_r + q * 4 * CH));
        float lo = __uint_as_float((unsigned)(a2 & 0xffffffffull));
        float hi = __uint_as_float((unsigned)(a2 >> 32));

        float2 rr;
        rr.x = fmaxf(xw.x + lo, 0.0f);
        rr.y = fmaxf(xw.y + hi, 0.0f);

        *(float2*)&hid_out[((size_t)gb * T_ + s) * H_ + gc] = rr;
        if (s == T_ - 1)
            *(float2*)&hlast[gb * H_ + gc] = rr;

        // ---- epilogue rendezvous: warps 1..7 arrive, warp 0 syncs+releases
        if (s != T_ - 1) {
            if (p == 0) {
                asm volatile("bar.sync 1, %0;" :: "n"(TB) : "memory");
                if (tid == 0)
                    st_rel(&g_flag[bi][ci][0], (unsigned)(s + 1));
            } else {
                asm volatile("bar.arrive 1, %0;" :: "n"(TB) : "memory");
            }
        }
    }
}

// ---------------------------------------------------------------------------
// Kernel C: output_list[bt][o] = hid[bt]·W_out[o] + b_out[o]   (f32x2)
// 64x64 tile, 256 threads, cp.async depth-4 pipeline, FULL K (32 chunks).
// ---------------------------------------------------------------------------
#define OC 36           // chunk row stride (32 + 4 pad, 16B-aligned)
#define OBUF (64 * OC)  // floats per buffer

__device__ __forceinline__ void cp16(unsigned dst, const void* src) {
    asm volatile("cp.async.cg.shared.global [%0], [%1], 16;"
                 :: "r"(dst), "l"(src) : "memory");
}
__device__ __forceinline__ void cp_commit() {
    asm volatile("cp.async.commit_group;" ::: "memory");
}

__global__ void __launch_bounds__(256) out_kernel(
    const float* __restrict__ hid, const float* __restrict__ Wout,
    const float* __restrict__ bout, float* __restrict__ outp)
{
    extern __shared__ float osm[];
    float* hsA = osm;                 // 4 bufs x OBUF
    float* wsA = osm + 4 * OBUF;      // 4 bufs x OBUF

    const int tid = threadIdx.x;
    const int btb = blockIdx.x * 64;
    const int tx = tid & 15, ty = tid >> 4;

    const float4* hid4  = (const float4*)hid;
    const float4* wout4 = (const float4*)Wout;

    const unsigned hs_base  = (unsigned)__cvta_generic_to_shared(hsA);
    const unsigned ws_base  = (unsigned)__cvta_generic_to_shared(wsA);
    const unsigned buf_step = OBUF * 4;

    auto issue = [&](int c, int b) {
        #pragma unroll
        for (int k = 0; k < 2; ++k) {
            int idx = k * 256 + tid;
            int r = idx >> 3, f = idx & 7;
            unsigned off = (unsigned)(r * OC + f * 4) * 4u + (unsigned)b * buf_step;
            cp16(hs_base + off, &hid4[(btb + r) * 256 + c * 8 + f]);
            cp16(ws_base + off, &wout4[r * 256 + c * 8 + f]);
        }
        cp_commit();
    };

    ull acc[4][4];
    #pragma unroll
    for (int i = 0; i < 4; ++i)
        #pragma unroll
        for (int j = 0; j < 4; ++j) acc[i][j] = 0ull;

    issue(0, 0); issue(1, 1); issue(2, 2); issue(3, 3);

    #pragma unroll 1
    for (int c = 0; c < 32; ++c) {
        if (c < 29)      asm volatile("cp.async.wait_group 3;" ::: "memory");
        else if (c == 29) asm volatile("cp.async.wait_group 2;" ::: "memory");
        else if (c == 30) asm volatile("cp.async.wait_group 1;" ::: "memory");
        else              asm volatile("cp.async.wait_group 0;" ::: "memory");
        __syncthreads();

        const int b = c & 3;
        const float* hb = hsA + b * OBUF;
        const float* wb = wsA + b * OBUF;

        #pragma unroll
        for (int k4 = 0; k4 < 8; ++k4) {
            ull2 a2[4], b2[4];
            #pragma unroll
            for (int i = 0; i < 4; ++i)
                a2[i] = *(const ull2*)&hb[(ty + 16 * i) * OC + k4 * 4];
            #pragma unroll
            for (int j = 0; j < 4; ++j)
                b2[j] = *(const ull2*)&wb[(tx + 16 * j) * OC + k4 * 4];
            #pragma unroll
            for (int i = 0; i < 4; ++i)
                #pragma unroll
                for (int j = 0; j < 4; ++j) {
                    acc[i][j] = f2fma(a2[i].x, b2[j].x, acc[i][j]);
                    acc[i][j] = f2fma(a2[i].y, b2[j].y, acc[i][j]);
                }
        }
        __syncthreads();

        if (c + 4 <= 31) issue(c + 4, (c + 4) & 3);
    }

    #pragma unroll
    for (int j = 0; j < 4; ++j) {
        int o = tx + 16 * j;
        float bb = bout[o];
        #pragma unroll
        for (int i = 0; i < 4; ++i)
            outp[(btb + ty + 16 * i) * O_ + o] = pairsum(acc[i][j]) + bb;
    }
}

// ---------------------------------------------------------------------------
extern "C" void kernel_launch(void* const* d_in, const int* in_sizes, int n_in,
                              void* d_out, int out_size) {
    const float* x      = (const float*)d_in[0];
    const float* hidden = (const float*)d_in[1];
    const float* W_ih   = (const float*)d_in[2];
    const float* W_hh   = (const float*)d_in[3];
    const float* b_ih   = (const float*)d_in[4];
    const float* b_hh   = (const float*)d_in[5];
    const float* W_out  = (const float*)d_in[6];
    const float* b_out  = (const float*)d_in[7];
    float* out = (float*)d_out;

    // A: 128x64 tiles, dynamic smem 50,688 B
    size_t smemA = (size_t)(128 * 66 + 64 * 66) * sizeof(float);
    cudaFuncSetAttribute(xw_kernel, cudaFuncAttributeMaxDynamicSharedMemorySize,
                         (int)smemA);
    dim3 gA(H_ / 64, (B_ * T_) / 128);   // 16 x 256
    xw_kernel<<<gA, 256, smemA>>>(x, W_ih, b_ih, b_hh, out + HID_OFF);

    // B: SMEM 4*WQ + 16*HRow = 52,352 floats = 209,408 B
    size_t smemB = (size_t)(4 * WQ + 16 * HRow) * sizeof(float);
    cudaFuncSetAttribute(rnn_recur, cudaFuncAttributeMaxDynamicSharedMemorySize,
                         (int)smemB);
    rnn_recur<<<NBLK, TB, smemB>>>(hidden, W_hh, out);

    // C: depth-4 pipeline, dynamic smem 73,728 B
    size_t smemC = (size_t)(8 * OBUF) * sizeof(float);
    cudaFuncSetAttribute(out_kernel, cudaFuncAttributeMaxDynamicSharedMemorySize,
                         (int)smemC);
    out_kernel<<<(B_ * T_) / 64, 256, smemC>>>(out + HID_OFF, W_out, b_out,
                                               out + OUT_OFF);
}